// round 1
// baseline (speedup 1.0000x reference)
#include <cuda_runtime.h>
#include <math.h>
#include <stdint.h>

// Problem constants
#define B_Q   256
#define M_MEM 200000
#define D_DIM 384
#define H_DIM 512
#define TOPK  5
#define TM    128                       // memory rows per sims CTA
#define NSLAB ((M_MEM + TM - 1) / TM)   // 1563

// ---------------- device scratch (static, allowed) ----------------
__device__ float g_center[2];
__device__ float g_act[M_MEM];
__device__ float g_qn[B_Q * D_DIM];
__device__ float g_cand_val[(size_t)NSLAB * B_Q * TOPK];
__device__ int   g_cand_idx[(size_t)NSLAB * B_Q * TOPK];
__device__ int   g_topk[B_Q * TOPK];

// ---------------- helpers ----------------
__device__ __forceinline__ bool better(float v, int i, float w, int j) {
    return (v > w) || (v == w && i < j);
}

// keep (tv, ti) sorted descending, 5 entries
__device__ __forceinline__ void ins5(float v, int i, float tv[TOPK], int ti[TOPK]) {
    if (!better(v, i, tv[TOPK - 1], ti[TOPK - 1])) return;
#pragma unroll
    for (int r = 0; r < TOPK; r++) {
        if (better(v, i, tv[r], ti[r])) {
            float fv = tv[r]; int fi = ti[r];
            tv[r] = v; ti[r] = i;
            v = fv; i = fi;
        }
    }
}

// ---------------- kernel A0: center of spatial_weights ----------------
__global__ void k_center(const float* __restrict__ sw) {
    __shared__ float sx[256], sy[256];
    int tid = threadIdx.x;
    float x = 0.f, y = 0.f;
    for (int i = tid; i < H_DIM; i += 256) { x += sw[2 * i]; y += sw[2 * i + 1]; }
    sx[tid] = x; sy[tid] = y;
    __syncthreads();
    for (int o = 128; o > 0; o >>= 1) {
        if (tid < o) { sx[tid] += sx[tid + o]; sy[tid] += sy[tid + o]; }
        __syncthreads();
    }
    if (tid == 0) {
        g_center[0] = sx[0] / (float)H_DIM;
        g_center[1] = sy[0] / (float)H_DIM;
    }
}

// ---------------- kernel A1: spatial activations ----------------
__global__ void k_act(const float* __restrict__ coords) {
    int i = blockIdx.x * blockDim.x + threadIdx.x;
    if (i < M_MEM) {
        float dx = coords[2 * i]     - g_center[0];
        float dy = coords[2 * i + 1] - g_center[1];
        float d = sqrtf(dx * dx + dy * dy);
        g_act[i] = 1.0f / (1.0f + d);
    }
}

// ---------------- kernel A2: normalize queries ----------------
__global__ void k_qnorm(const float* __restrict__ q) {
    __shared__ float red[128];
    int b = blockIdx.x, tid = threadIdx.x;
    float s = 0.f;
    for (int d = tid; d < D_DIM; d += 128) {
        float v = q[(size_t)b * D_DIM + d];
        s += v * v;
    }
    red[tid] = s;
    __syncthreads();
    for (int o = 64; o > 0; o >>= 1) {
        if (tid < o) red[tid] += red[tid + o];
        __syncthreads();
    }
    float r = 1.0f / fmaxf(sqrtf(red[0]), 1e-8f);
    for (int d = tid; d < D_DIM; d += 128)
        g_qn[(size_t)b * D_DIM + d] = q[(size_t)b * D_DIM + d] * r;
}

// ---------------- kernel B: sims SGEMM + fused local top-5 ----------------
struct GemmBufs { float Qs[2][16][128]; float Ms[2][16][128]; };
union  SmemU    { GemmBufs g; float sims[64][128]; float part[256]; };
struct __align__(16) SmemB { SmemU u; float rn[128]; float act[128]; };

__global__ __launch_bounds__(256, 2) void k_sims(const float* __restrict__ mem) {
    __shared__ SmemB sm;
    const int tid = threadIdx.x;
    const int tx = tid & 15;        // query sub-tile
    const int ty = tid >> 4;        // memory sub-tile
    const int bx = blockIdx.x, by = blockIdx.y;
    const int m0 = bx * TM, q0 = by * 128;

    // --- memory-row norm pre-pass (also warms cache for GEMM) ---
    {
        int row = tid >> 1, half = tid & 1;
        int rg = m0 + row; if (rg >= M_MEM) rg = M_MEM - 1;
        const float4* p = (const float4*)(mem + (size_t)rg * D_DIM + half * 192);
        float s = 0.f;
#pragma unroll
        for (int i = 0; i < 48; i++) {
            float4 v = p[i];
            s += v.x * v.x + v.y * v.y + v.z * v.z + v.w * v.w;
        }
        sm.u.part[tid] = s;
    }
    __syncthreads();
    if (tid < 128) {
        float s = sm.u.part[2 * tid] + sm.u.part[2 * tid + 1];
        bool ok = (m0 + tid) < M_MEM;
        sm.rn[tid]  = ok ? 1.0f / fmaxf(sqrtf(s), 1e-8f) : 0.0f;
        sm.act[tid] = ok ? g_act[m0 + tid] : -1e30f;
    }
    __syncthreads();

    // --- GEMM: acc[i][j] = sum_k mem[m0+ty*8+i][k] * qn[q0+tx*8+j][k] ---
    const int lf = (tid & 3) * 4;   // k offset within 16-tile
    const int lr = tid >> 2;        // row 0..63 (second row at +64)
    const float* qb1 = g_qn + (size_t)(q0 + lr) * D_DIM + lf;
    const float* qb2 = g_qn + (size_t)(q0 + lr + 64) * D_DIM + lf;
    int mrA = m0 + lr;      if (mrA >= M_MEM) mrA = M_MEM - 1;
    int mrB = m0 + lr + 64; if (mrB >= M_MEM) mrB = M_MEM - 1;
    const float* mb1 = mem + (size_t)mrA * D_DIM + lf;
    const float* mb2 = mem + (size_t)mrB * D_DIM + lf;

    float acc[8][8];
#pragma unroll
    for (int i = 0; i < 8; i++)
#pragma unroll
        for (int j = 0; j < 8; j++) acc[i][j] = 0.f;

#define STORE_TILES(nbuf, A0, A1, Bm0, Bm1) do {                                  \
    sm.u.g.Qs[nbuf][lf + 0][lr] = (A0).x;  sm.u.g.Qs[nbuf][lf + 1][lr] = (A0).y;  \
    sm.u.g.Qs[nbuf][lf + 2][lr] = (A0).z;  sm.u.g.Qs[nbuf][lf + 3][lr] = (A0).w;  \
    sm.u.g.Qs[nbuf][lf + 0][lr + 64] = (A1).x; sm.u.g.Qs[nbuf][lf + 1][lr + 64] = (A1).y; \
    sm.u.g.Qs[nbuf][lf + 2][lr + 64] = (A1).z; sm.u.g.Qs[nbuf][lf + 3][lr + 64] = (A1).w; \
    sm.u.g.Ms[nbuf][lf + 0][lr] = (Bm0).x; sm.u.g.Ms[nbuf][lf + 1][lr] = (Bm0).y; \
    sm.u.g.Ms[nbuf][lf + 2][lr] = (Bm0).z; sm.u.g.Ms[nbuf][lf + 3][lr] = (Bm0).w; \
    sm.u.g.Ms[nbuf][lf + 0][lr + 64] = (Bm1).x; sm.u.g.Ms[nbuf][lf + 1][lr + 64] = (Bm1).y; \
    sm.u.g.Ms[nbuf][lf + 2][lr + 64] = (Bm1).z; sm.u.g.Ms[nbuf][lf + 3][lr + 64] = (Bm1).w; \
} while (0)

    {
        float4 a0 = *(const float4*)(qb1);
        float4 a1 = *(const float4*)(qb2);
        float4 b0 = *(const float4*)(mb1);
        float4 b1 = *(const float4*)(mb2);
        STORE_TILES(0, a0, a1, b0, b1);
    }
    __syncthreads();

#pragma unroll 1
    for (int kt = 0; kt < 24; kt++) {
        const int cb = kt & 1, nbuf = cb ^ 1;
        float4 na0, na1, nb0, nb1;
        if (kt < 23) {
            na0 = *(const float4*)(qb1 + (kt + 1) * 16);
            na1 = *(const float4*)(qb2 + (kt + 1) * 16);
            nb0 = *(const float4*)(mb1 + (kt + 1) * 16);
            nb1 = *(const float4*)(mb2 + (kt + 1) * 16);
        }
#pragma unroll
        for (int k = 0; k < 16; k++) {
            float a[8], b[8];
            *(float4*)&a[0] = *(const float4*)&sm.u.g.Qs[cb][k][tx * 8];
            *(float4*)&a[4] = *(const float4*)&sm.u.g.Qs[cb][k][tx * 8 + 4];
            *(float4*)&b[0] = *(const float4*)&sm.u.g.Ms[cb][k][ty * 8];
            *(float4*)&b[4] = *(const float4*)&sm.u.g.Ms[cb][k][ty * 8 + 4];
#pragma unroll
            for (int i = 0; i < 8; i++)
#pragma unroll
                for (int j = 0; j < 8; j++)
                    acc[i][j] = fmaf(b[i], a[j], acc[i][j]);
        }
        if (kt < 23) {
            __syncthreads();
            STORE_TILES(nbuf, na0, na1, nb0, nb1);
            __syncthreads();
        }
    }
    __syncthreads();

    // --- epilogue: scale by 1/||m||, add activation, local top-5 per query ---
    float tv[TOPK]; int ti[TOPK];
#pragma unroll
    for (int r = 0; r < TOPK; r++) { tv[r] = -3.4e38f; ti[r] = 0x7fffffff; }

    for (int phase = 0; phase < 2; phase++) {
        if ((ty >> 3) == phase) {
#pragma unroll
            for (int i = 0; i < 8; i++) {
                int gr = ty * 8 + i;          // 0..127 within tile
                int r  = gr - phase * 64;     // 0..63 in staging buffer
                float scale = sm.rn[gr], bias = sm.act[gr];
#pragma unroll
                for (int j = 0; j < 8; j++)
                    sm.u.sims[r][tx * 8 + j] = acc[i][j] * scale + bias;
            }
        }
        __syncthreads();
        if (tid < 128) {
            for (int r = 0; r < 64; r++)
                ins5(sm.u.sims[r][tid], m0 + phase * 64 + r, tv, ti);
        }
        __syncthreads();
    }

    if (tid < 128) {
        size_t base = ((size_t)bx * B_Q + (q0 + tid)) * TOPK;
#pragma unroll
        for (int r = 0; r < TOPK; r++) {
            g_cand_val[base + r] = tv[r];
            g_cand_idx[base + r] = ti[r];
        }
    }
#undef STORE_TILES
}

// ---------------- kernel C: merge slab candidates -> global top-5 ----------------
__device__ __forceinline__ void merge5(float* av, int* ai, const float* bv, const int* bi) {
    float ov[TOPK]; int oi[TOPK];
    int ia = 0, ib = 0;
#pragma unroll
    for (int r = 0; r < TOPK; r++) {
        bool ta = (ib >= TOPK) || (ia < TOPK && better(av[ia], ai[ia], bv[ib], bi[ib]));
        if (ta) { ov[r] = av[ia]; oi[r] = ai[ia]; ia++; }
        else    { ov[r] = bv[ib]; oi[r] = bi[ib]; ib++; }
    }
#pragma unroll
    for (int r = 0; r < TOPK; r++) { av[r] = ov[r]; ai[r] = oi[r]; }
}

__global__ void k_merge() {
    const int q = blockIdx.x, tid = threadIdx.x;
    float tv[TOPK]; int ti[TOPK];
#pragma unroll
    for (int r = 0; r < TOPK; r++) { tv[r] = -3.4e38f; ti[r] = 0x7fffffff; }

    for (int s = tid; s < NSLAB; s += 256) {
        size_t base = ((size_t)s * B_Q + q) * TOPK;
#pragma unroll
        for (int r = 0; r < TOPK; r++)
            ins5(g_cand_val[base + r], g_cand_idx[base + r], tv, ti);
    }

    __shared__ float sv[256][TOPK];
    __shared__ int   si[256][TOPK];
#pragma unroll
    for (int r = 0; r < TOPK; r++) { sv[tid][r] = tv[r]; si[tid][r] = ti[r]; }
    __syncthreads();
    for (int o = 128; o > 0; o >>= 1) {
        if (tid < o) merge5(sv[tid], si[tid], sv[tid + o], si[tid + o]);
        __syncthreads();
    }
    if (tid == 0) {
#pragma unroll
        for (int r = 0; r < TOPK; r++)
            g_topk[q * TOPK + r] = si[0][r];
    }
}

// ---------------- kernel D: RNN + gating epilogue ----------------
// 32 blocks x 256 threads, 8 queries per block; thread owns h = tid and tid+256.
__global__ __launch_bounds__(256) void k_rnn(
    const float* __restrict__ query, const float* __restrict__ mem,
    const float* __restrict__ Wih, const float* __restrict__ bih,
    const float* __restrict__ Whh, const float* __restrict__ bhh,
    const float* __restrict__ gW,  const float* __restrict__ gb,
    float* __restrict__ out)
{
    __shared__ __align__(16) float inp[8][D_DIM];
    __shared__ __align__(16) float hbuf[2][8][H_DIM];

    const int tid = threadIdx.x;
    const int qb = blockIdx.x * 8;
    const int h0 = tid, h1 = tid + 256;

    // load 8 query rows
    for (int i = tid; i < 8 * D_DIM; i += 256) {
        int q = i / D_DIM, d = i % D_DIM;
        inp[q][d] = query[(size_t)(qb + q) * D_DIM + d];
    }
    __syncthreads();

    float xp0a[8], xp0b[8], gata[8], gatb[8];
    // x_proj for t=0 (== projected_query)
    {
        float a0[8], a1[8];
#pragma unroll
        for (int q = 0; q < 8; q++) { a0[q] = 0.f; a1[q] = 0.f; }
        const float4* w0 = (const float4*)(Wih + (size_t)h0 * D_DIM);
        const float4* w1 = (const float4*)(Wih + (size_t)h1 * D_DIM);
        for (int d4 = 0; d4 < D_DIM / 4; d4++) {
            float4 wa = w0[d4], wb = w1[d4];
#pragma unroll
            for (int q = 0; q < 8; q++) {
                float4 x = ((const float4*)inp[q])[d4];
                a0[q] += wa.x * x.x + wa.y * x.y + wa.z * x.z + wa.w * x.w;
                a1[q] += wb.x * x.x + wb.y * x.y + wb.z * x.z + wb.w * x.w;
            }
        }
        float ba = bih[h0], bb = bih[h1];
#pragma unroll
        for (int q = 0; q < 8; q++) { xp0a[q] = a0[q] + ba; xp0b[q] = a1[q] + bb; }
    }
    // gate
    {
        float a0[8], a1[8];
#pragma unroll
        for (int q = 0; q < 8; q++) { a0[q] = 0.f; a1[q] = 0.f; }
        const float4* w0 = (const float4*)(gW + (size_t)h0 * D_DIM);
        const float4* w1 = (const float4*)(gW + (size_t)h1 * D_DIM);
        for (int d4 = 0; d4 < D_DIM / 4; d4++) {
            float4 wa = w0[d4], wb = w1[d4];
#pragma unroll
            for (int q = 0; q < 8; q++) {
                float4 x = ((const float4*)inp[q])[d4];
                a0[q] += wa.x * x.x + wa.y * x.y + wa.z * x.z + wa.w * x.w;
                a1[q] += wb.x * x.x + wb.y * x.y + wb.z * x.z + wb.w * x.w;
            }
        }
        float ba = gb[h0], bb = gb[h1];
#pragma unroll
        for (int q = 0; q < 8; q++) {
            gata[q] = 1.0f / (1.0f + expf(-(a0[q] + ba)));
            gatb[q] = 1.0f / (1.0f + expf(-(a1[q] + bb)));
        }
    }

    // step 0: h = tanh(xp0 + b_hh)
    {
        float ba = bhh[h0], bb = bhh[h1];
#pragma unroll
        for (int q = 0; q < 8; q++) {
            hbuf[0][q][h0] = tanhf(xp0a[q] + ba);
            hbuf[0][q][h1] = tanhf(xp0b[q] + bb);
        }
    }
    __syncthreads();

    int cur = 0;
    for (int t = 1; t <= TOPK; t++) {
        // gather retrieved vectors for this step
        for (int i = tid; i < 8 * D_DIM; i += 256) {
            int q = i / D_DIM, d = i % D_DIM;
            int mi = g_topk[(qb + q) * TOPK + (t - 1)];
            inp[q][d] = mem[(size_t)mi * D_DIM + d];
        }
        __syncthreads();

        float a0[8], a1[8];
#pragma unroll
        for (int q = 0; q < 8; q++) { a0[q] = 0.f; a1[q] = 0.f; }
        // input projection
        {
            const float4* w0 = (const float4*)(Wih + (size_t)h0 * D_DIM);
            const float4* w1 = (const float4*)(Wih + (size_t)h1 * D_DIM);
            for (int d4 = 0; d4 < D_DIM / 4; d4++) {
                float4 wa = w0[d4], wb = w1[d4];
#pragma unroll
                for (int q = 0; q < 8; q++) {
                    float4 x = ((const float4*)inp[q])[d4];
                    a0[q] += wa.x * x.x + wa.y * x.y + wa.z * x.z + wa.w * x.w;
                    a1[q] += wb.x * x.x + wb.y * x.y + wb.z * x.z + wb.w * x.w;
                }
            }
        }
        // recurrent projection
        {
            const float4* w0 = (const float4*)(Whh + (size_t)h0 * H_DIM);
            const float4* w1 = (const float4*)(Whh + (size_t)h1 * H_DIM);
            for (int d4 = 0; d4 < H_DIM / 4; d4++) {
                float4 wa = w0[d4], wb = w1[d4];
#pragma unroll
                for (int q = 0; q < 8; q++) {
                    float4 hh = ((const float4*)hbuf[cur][q])[d4];
                    a0[q] += wa.x * hh.x + wa.y * hh.y + wa.z * hh.z + wa.w * hh.w;
                    a1[q] += wb.x * hh.x + wb.y * hh.y + wb.z * hh.z + wb.w * hh.w;
                }
            }
        }
        float bia = bih[h0], bib = bih[h1];
        float bha = bhh[h0], bhb = bhh[h1];
#pragma unroll
        for (int q = 0; q < 8; q++) {
            hbuf[cur ^ 1][q][h0] = tanhf(a0[q] + bia + bha);
            hbuf[cur ^ 1][q][h1] = tanhf(a1[q] + bib + bhb);
        }
        __syncthreads();
        cur ^= 1;
    }

    // output: gate*h + (1-gate)*projected_query
#pragma unroll
    for (int q = 0; q < 8; q++) {
        float ha = hbuf[cur][q][h0];
        float hb = hbuf[cur][q][h1];
        out[(size_t)(qb + q) * H_DIM + h0] = gata[q] * ha + (1.0f - gata[q]) * xp0a[q];
        out[(size_t)(qb + q) * H_DIM + h1] = gatb[q] * hb + (1.0f - gatb[q]) * xp0b[q];
    }
}

// ---------------- launch ----------------
extern "C" void kernel_launch(void* const* d_in, const int* in_sizes, int n_in,
                              void* d_out, int out_size) {
    const float* query  = (const float*)d_in[0];
    const float* mem    = (const float*)d_in[1];
    const float* coords = (const float*)d_in[2];
    const float* sw     = (const float*)d_in[3];
    const float* Wih    = (const float*)d_in[4];
    const float* bih    = (const float*)d_in[5];
    const float* Whh    = (const float*)d_in[6];
    const float* bhh    = (const float*)d_in[7];
    const float* gW     = (const float*)d_in[8];
    const float* gb     = (const float*)d_in[9];
    float* out = (float*)d_out;

    k_center<<<1, 256>>>(sw);
    k_act<<<(M_MEM + 255) / 256, 256>>>(coords);
    k_qnorm<<<B_Q, 128>>>(query);
    dim3 gs(NSLAB, 2);
    k_sims<<<gs, 256>>>(mem);
    k_merge<<<B_Q, 256>>>();
    k_rnn<<<32, 256>>>(query, mem, Wih, bih, Whh, bhh, gW, gb, out);
}

// round 3
// speedup vs baseline: 1.2945x; 1.2945x over previous
#include <cuda_runtime.h>
#include <cuda_bf16.h>
#include <math.h>
#include <stdint.h>

// Problem constants
#define B_Q   256
#define M_MEM 200000
#define D_DIM 384
#define H_DIM 512
#define TOPK  5
#define TM    128
#define NSLAB ((M_MEM + TM - 1) / TM)   // 1563

// ---------------- device scratch ----------------
__device__ float g_center[2];
__device__ float g_act[M_MEM];
__device__ __align__(16) __nv_bfloat16 g_qhi[B_Q * D_DIM];
__device__ __align__(16) __nv_bfloat16 g_qlo[B_Q * D_DIM];
__device__ float g_cand_val[(size_t)NSLAB * B_Q * TOPK];
__device__ int   g_cand_idx[(size_t)NSLAB * B_Q * TOPK];
__device__ int   g_topk[B_Q * TOPK];

// ---------------- helpers ----------------
__device__ __forceinline__ uint32_t smem_u32(const void* p) {
    uint32_t a;
    asm("{ .reg .u64 t; cvta.to.shared.u64 t, %1; cvt.u32.u64 %0, t; }" : "=r"(a) : "l"(p));
    return a;
}
#define CPA16(s, g)  asm volatile("cp.async.cg.shared.global [%0], [%1], 16;" :: "r"(s), "l"(g) : "memory")
#define CPA_COMMIT() asm volatile("cp.async.commit_group;" ::: "memory")
#define CPA_WAIT0()  asm volatile("cp.async.wait_group 0;" ::: "memory")

__device__ __forceinline__ void ldsm4(uint32_t* r, uint32_t addr) {
    asm volatile("ldmatrix.sync.aligned.m8n8.x4.shared.b16 {%0,%1,%2,%3}, [%4];"
        : "=r"(r[0]), "=r"(r[1]), "=r"(r[2]), "=r"(r[3]) : "r"(addr));
}
__device__ __forceinline__ void mma16816(float* d, const uint32_t* a, uint32_t b0, uint32_t b1) {
    asm volatile("mma.sync.aligned.m16n8k16.row.col.f32.bf16.bf16.f32 "
        "{%0,%1,%2,%3}, {%4,%5,%6,%7}, {%8,%9}, {%0,%1,%2,%3};"
        : "+f"(d[0]), "+f"(d[1]), "+f"(d[2]), "+f"(d[3])
        : "r"(a[0]), "r"(a[1]), "r"(a[2]), "r"(a[3]), "r"(b0), "r"(b1));
}

__device__ __forceinline__ bool better(float v, int i, float w, int j) {
    return (v > w) || (v == w && i < j);
}
__device__ __forceinline__ void ins5(float v, int i, float tv[TOPK], int ti[TOPK]) {
    if (!better(v, i, tv[TOPK - 1], ti[TOPK - 1])) return;
#pragma unroll
    for (int r = 0; r < TOPK; r++) {
        if (better(v, i, tv[r], ti[r])) {
            float fv = tv[r]; int fi = ti[r];
            tv[r] = v; ti[r] = i;
            v = fv; i = fi;
        }
    }
}

// ---------------- kernel A0: center ----------------
__global__ void k_center(const float* __restrict__ sw) {
    __shared__ float sx[256], sy[256];
    int tid = threadIdx.x;
    float x = 0.f, y = 0.f;
    for (int i = tid; i < H_DIM; i += 256) { x += sw[2 * i]; y += sw[2 * i + 1]; }
    sx[tid] = x; sy[tid] = y;
    __syncthreads();
    for (int o = 128; o > 0; o >>= 1) {
        if (tid < o) { sx[tid] += sx[tid + o]; sy[tid] += sy[tid + o]; }
        __syncthreads();
    }
    if (tid == 0) {
        g_center[0] = sx[0] / (float)H_DIM;
        g_center[1] = sy[0] / (float)H_DIM;
    }
}

// ---------------- kernel A1: activations ----------------
__global__ void k_act(const float* __restrict__ coords) {
    int i = blockIdx.x * blockDim.x + threadIdx.x;
    if (i < M_MEM) {
        float dx = coords[2 * i]     - g_center[0];
        float dy = coords[2 * i + 1] - g_center[1];
        g_act[i] = 1.0f / (1.0f + sqrtf(dx * dx + dy * dy));
    }
}

// ---------------- kernel A2: normalize queries -> bf16 hi/lo ----------------
__global__ void k_qnorm(const float* __restrict__ q) {
    __shared__ float red[128];
    int b = blockIdx.x, tid = threadIdx.x;
    float s = 0.f;
    for (int d = tid; d < D_DIM; d += 128) {
        float v = q[(size_t)b * D_DIM + d];
        s += v * v;
    }
    red[tid] = s;
    __syncthreads();
    for (int o = 64; o > 0; o >>= 1) {
        if (tid < o) red[tid] += red[tid + o];
        __syncthreads();
    }
    float r = 1.0f / fmaxf(sqrtf(red[0]), 1e-8f);
    for (int d = tid; d < D_DIM; d += 128) {
        float qn = q[(size_t)b * D_DIM + d] * r;
        __nv_bfloat16 h = __float2bfloat16(qn);
        g_qhi[(size_t)b * D_DIM + d] = h;
        g_qlo[(size_t)b * D_DIM + d] = __float2bfloat16(qn - __bfloat162float(h));
    }
}

// ---------------- kernel B: mma.sync bf16 hi/lo sims + fused top-5 ----------------
// smem layout (dynamic):
#define PADB   272                    // bytes per 128-bf16 padded row (136 elems)
#define OFF_RN  0                     // 128 f32
#define OFF_ACT 512                   // 128 f32
#define OFF_RED 1024                  // 512 f32 reduce scratch
#define OFF_AH  4096
#define A_BYTES (128 * PADB)          // 34816
#define OFF_AL  (OFF_AH + A_BYTES)    // 38912
#define OFF_BH  (OFF_AL + A_BYTES)    // 73728
#define B_BYTES (256 * PADB)          // 69632
#define OFF_BL  (OFF_BH + B_BYTES)    // 143360
#define SMEM_SIMS (OFF_BL + B_BYTES)  // 212992
// epilogue reuse (after GEMM):
#define OFF_STG 4096                  // [256][132] f32 = 135168
#define OFF_PV  (OFF_STG + 135168)    // 512*5 f32
#define OFF_PI  (OFF_PV + 10240)      // 512*5 int

__global__ __launch_bounds__(512, 1) void k_sims_mma(const float* __restrict__ mem) {
    extern __shared__ char smem[];
    const uint32_t sb = smem_u32(smem);
    float* s_rn  = (float*)(smem + OFF_RN);
    float* s_act = (float*)(smem + OFF_ACT);
    float* s_red = (float*)(smem + OFF_RED);

    const int tid = threadIdx.x;
    const int l   = tid & 31;
    const int w   = tid >> 5;       // 0..15
    const int wm  = w & 3;          // m tile: rows wm*32..+32
    const int wn  = w >> 2;         // n tile: cols wn*64..+64
    const int m0  = blockIdx.x * TM;

    // --- norm pre-pass (single DRAM read of the slab; warms L2 for conversion) ---
    {
        int prow = tid >> 2, pq = tid & 3;
        int prg = m0 + prow; if (prg >= M_MEM) prg = M_MEM - 1;
        const float4* p = (const float4*)(mem + (size_t)prg * D_DIM + pq * 96);
        float s = 0.f;
#pragma unroll
        for (int i = 0; i < 24; i++) {
            float4 v = p[i];
            s += v.x * v.x + v.y * v.y + v.z * v.z + v.w * v.w;
        }
        s_red[tid] = s;
    }
    __syncthreads();
    if (tid < 128) {
        float s = s_red[4 * tid] + s_red[4 * tid + 1] + s_red[4 * tid + 2] + s_red[4 * tid + 3];
        bool ok = (m0 + tid) < M_MEM;
        s_rn[tid]  = ok ? 1.0f / fmaxf(sqrtf(s), 1e-8f) : 0.0f;
        s_act[tid] = ok ? g_act[m0 + tid] : -1e30f;
    }

    // --- accumulators: warp tile 32x64 = acc[2 m-atoms][8 n-atoms][4] ---
    float acc[2][8][4];
#pragma unroll
    for (int a = 0; a < 2; a++)
#pragma unroll
        for (int p = 0; p < 8; p++)
#pragma unroll
            for (int r = 0; r < 4; r++) acc[a][p][r] = 0.f;

    // A fp32 source (clamped row)
    const int arow = tid >> 2, aq = tid & 3;
    int arg = m0 + arow; if (arg >= M_MEM) arg = M_MEM - 1;
    const float4* asrc = (const float4*)(mem + (size_t)arg * D_DIM + aq * 32);

    // per-lane ldmatrix base addresses
    const uint32_t a_ld = sb + OFF_AH + (uint32_t)((wm * 32 + (l & 15)) * PADB + (l >> 4) * 16);
    const uint32_t b_ld = sb + OFF_BH + (uint32_t)((wn * 64 + (l & 15)) * PADB + (l >> 4) * 16);

#pragma unroll 1
    for (int c = 0; c < 3; c++) {
        __syncthreads();  // previous chunk's GEMM reads done before overwrite

        // B chunk: queries hi/lo via cp.async into padded smem
#pragma unroll
        for (int i = 0; i < 8; i++) {
            int idx = i * 512 + tid;
            int row = idx >> 4, s16 = idx & 15;
            uint32_t dst = sb + (uint32_t)(row * PADB + s16 * 16);
            size_t goff = (size_t)row * D_DIM + c * 128 + s16 * 8;
            CPA16(dst + OFF_BH, (const void*)(g_qhi + goff));
            CPA16(dst + OFF_BL, (const void*)(g_qlo + goff));
        }
        CPA_COMMIT();

        // A chunk: fp32 (L2-hot) -> bf16 hi/lo -> padded smem
        {
            char* ah = smem + OFF_AH;
            char* al = smem + OFF_AL;
#pragma unroll
            for (int i = 0; i < 8; i++) {
                float4 v = asrc[c * 32 + i];
                __nv_bfloat16 hx = __float2bfloat16(v.x), hy = __float2bfloat16(v.y);
                __nv_bfloat16 hz = __float2bfloat16(v.z), hw = __float2bfloat16(v.w);
                __nv_bfloat16 lx = __float2bfloat16(v.x - __bfloat162float(hx));
                __nv_bfloat16 ly = __float2bfloat16(v.y - __bfloat162float(hy));
                __nv_bfloat16 lz = __float2bfloat16(v.z - __bfloat162float(hz));
                __nv_bfloat16 lw = __float2bfloat16(v.w - __bfloat162float(hw));
                __nv_bfloat162 h0 = __halves2bfloat162(hx, hy);
                __nv_bfloat162 h1 = __halves2bfloat162(hz, hw);
                __nv_bfloat162 l0 = __halves2bfloat162(lx, ly);
                __nv_bfloat162 l1 = __halves2bfloat162(lz, lw);
                uint32_t so = (uint32_t)(arow * PADB + aq * 64 + i * 8);
                *(uint2*)(ah + so) = make_uint2(*(uint32_t*)&h0, *(uint32_t*)&h1);
                *(uint2*)(al + so) = make_uint2(*(uint32_t*)&l0, *(uint32_t*)&l1);
            }
        }
        CPA_WAIT0();
        __syncthreads();

        // --- GEMM: 8 k16 steps over this chunk ---
#pragma unroll 1
        for (int kk = 0; kk < 8; kk++) {
            uint32_t bh[16], bl[16];
#pragma unroll
            for (int pp = 0; pp < 4; pp++) {
                uint32_t ba = b_ld + (uint32_t)(pp * 16 * PADB + kk * 32);
                ldsm4(bh + pp * 4, ba);
                ldsm4(bl + pp * 4, ba + (OFF_BL - OFF_BH));
            }
#pragma unroll
            for (int a = 0; a < 2; a++) {
                uint32_t ah4[4], al4[4];
                uint32_t aa = a_ld + (uint32_t)(a * 16 * PADB + kk * 32);
                ldsm4(ah4, aa);
                ldsm4(al4, aa + (OFF_AL - OFF_AH));
#pragma unroll
                for (int p = 0; p < 8; p++) {
                    int pp = p >> 1, hi = p & 1;
                    uint32_t b0h = bh[pp * 4 + hi], b1h = bh[pp * 4 + hi + 2];
                    uint32_t b0l = bl[pp * 4 + hi], b1l = bl[pp * 4 + hi + 2];
                    mma16816(acc[a][p], ah4, b0h, b1h);   // hi*hi
                    mma16816(acc[a][p], ah4, b0l, b1l);   // hi*lo
                    mma16816(acc[a][p], al4, b0h, b1h);   // lo*hi
                }
            }
        }
    }
    __syncthreads();

    // --- epilogue: scale + bias, stage query-major, fused top-5 ---
    float* stg = (float*)(smem + OFF_STG);
#pragma unroll
    for (int a = 0; a < 2; a++) {
        int mA = wm * 32 + a * 16 + (l >> 2);
        float rnA = s_rn[mA],     acA = s_act[mA];
        float rnB = s_rn[mA + 8], acB = s_act[mA + 8];
#pragma unroll
        for (int p = 0; p < 8; p++) {
            int q = wn * 64 + p * 8 + (l & 3) * 2;
            stg[q * 132 + mA]           = acc[a][p][0] * rnA + acA;
            stg[(q + 1) * 132 + mA]     = acc[a][p][1] * rnA + acA;
            stg[q * 132 + mA + 8]       = acc[a][p][2] * rnB + acB;
            stg[(q + 1) * 132 + mA + 8] = acc[a][p][3] * rnB + acB;
        }
    }
    __syncthreads();

    // per-thread top-5 over 64 rows of one query
    {
        float* pv = (float*)(smem + OFF_PV);
        int*   pi = (int*)(smem + OFF_PI);
        int q = tid >> 1, h = tid & 1;
        float tv[TOPK]; int ti[TOPK];
#pragma unroll
        for (int r = 0; r < TOPK; r++) { tv[r] = -3.4e38f; ti[r] = 0x7fffffff; }
        const float4* col = (const float4*)(stg + q * 132 + h * 64);
#pragma unroll 4
        for (int i = 0; i < 16; i++) {
            float4 v = col[i];
            int mb = m0 + h * 64 + i * 4;
            ins5(v.x, mb,     tv, ti);
            ins5(v.y, mb + 1, tv, ti);
            ins5(v.z, mb + 2, tv, ti);
            ins5(v.w, mb + 3, tv, ti);
        }
#pragma unroll
        for (int r = 0; r < TOPK; r++) { pv[tid * TOPK + r] = tv[r]; pi[tid * TOPK + r] = ti[r]; }
        __syncthreads();

        if (tid < 256) {
            float fv[TOPK]; int fi[TOPK];
#pragma unroll
            for (int r = 0; r < TOPK; r++) {
                fv[r] = pv[(2 * tid) * TOPK + r];
                fi[r] = pi[(2 * tid) * TOPK + r];
            }
#pragma unroll
            for (int r = 0; r < TOPK; r++)
                ins5(pv[(2 * tid + 1) * TOPK + r], pi[(2 * tid + 1) * TOPK + r], fv, fi);
            size_t base = ((size_t)blockIdx.x * B_Q + tid) * TOPK;
#pragma unroll
            for (int r = 0; r < TOPK; r++) {
                g_cand_val[base + r] = fv[r];
                g_cand_idx[base + r] = fi[r];
            }
        }
    }
}

// ---------------- kernel C: merge slab candidates ----------------
__device__ __forceinline__ void merge5(float* av, int* ai, const float* bv, const int* bi) {
    float ov[TOPK]; int oi[TOPK];
    int ia = 0, ib = 0;
#pragma unroll
    for (int r = 0; r < TOPK; r++) {
        bool ta = (ib >= TOPK) || (ia < TOPK && better(av[ia], ai[ia], bv[ib], bi[ib]));
        if (ta) { ov[r] = av[ia]; oi[r] = ai[ia]; ia++; }
        else    { ov[r] = bv[ib]; oi[r] = bi[ib]; ib++; }
    }
#pragma unroll
    for (int r = 0; r < TOPK; r++) { av[r] = ov[r]; ai[r] = oi[r]; }
}

__global__ void k_merge() {
    const int q = blockIdx.x, tid = threadIdx.x;
    float tv[TOPK]; int ti[TOPK];
#pragma unroll
    for (int r = 0; r < TOPK; r++) { tv[r] = -3.4e38f; ti[r] = 0x7fffffff; }

    for (int s = tid; s < NSLAB; s += 256) {
        size_t base = ((size_t)s * B_Q + q) * TOPK;
#pragma unroll
        for (int r = 0; r < TOPK; r++)
            ins5(g_cand_val[base + r], g_cand_idx[base + r], tv, ti);
    }

    __shared__ float sv[256][TOPK];
    __shared__ int   si[256][TOPK];
#pragma unroll
    for (int r = 0; r < TOPK; r++) { sv[tid][r] = tv[r]; si[tid][r] = ti[r]; }
    __syncthreads();
    for (int o = 128; o > 0; o >>= 1) {
        if (tid < o) merge5(sv[tid], si[tid], sv[tid + o], si[tid + o]);
        __syncthreads();
    }
    if (tid == 0) {
#pragma unroll
        for (int r = 0; r < TOPK; r++)
            g_topk[q * TOPK + r] = si[0][r];
    }
}

// ---------------- kernel D: RNN + gating epilogue ----------------
__global__ __launch_bounds__(256) void k_rnn(
    const float* __restrict__ query, const float* __restrict__ mem,
    const float* __restrict__ Wih, const float* __restrict__ bih,
    const float* __restrict__ Whh, const float* __restrict__ bhh,
    const float* __restrict__ gW,  const float* __restrict__ gb,
    float* __restrict__ out)
{
    __shared__ __align__(16) float inp[8][D_DIM];
    __shared__ __align__(16) float hbuf[2][8][H_DIM];

    const int tid = threadIdx.x;
    const int qb = blockIdx.x * 8;
    const int h0 = tid, h1 = tid + 256;

    for (int i = tid; i < 8 * D_DIM; i += 256) {
        int q = i / D_DIM, d = i % D_DIM;
        inp[q][d] = query[(size_t)(qb + q) * D_DIM + d];
    }
    __syncthreads();

    float xp0a[8], xp0b[8], gata[8], gatb[8];
    {
        float a0[8], a1[8];
#pragma unroll
        for (int q = 0; q < 8; q++) { a0[q] = 0.f; a1[q] = 0.f; }
        const float4* w0 = (const float4*)(Wih + (size_t)h0 * D_DIM);
        const float4* w1 = (const float4*)(Wih + (size_t)h1 * D_DIM);
        for (int d4 = 0; d4 < D_DIM / 4; d4++) {
            float4 wa = w0[d4], wb = w1[d4];
#pragma unroll
            for (int q = 0; q < 8; q++) {
                float4 x = ((const float4*)inp[q])[d4];
                a0[q] += wa.x * x.x + wa.y * x.y + wa.z * x.z + wa.w * x.w;
                a1[q] += wb.x * x.x + wb.y * x.y + wb.z * x.z + wb.w * x.w;
            }
        }
        float ba = bih[h0], bb = bih[h1];
#pragma unroll
        for (int q = 0; q < 8; q++) { xp0a[q] = a0[q] + ba; xp0b[q] = a1[q] + bb; }
    }
    {
        float a0[8], a1[8];
#pragma unroll
        for (int q = 0; q < 8; q++) { a0[q] = 0.f; a1[q] = 0.f; }
        const float4* w0 = (const float4*)(gW + (size_t)h0 * D_DIM);
        const float4* w1 = (const float4*)(gW + (size_t)h1 * D_DIM);
        for (int d4 = 0; d4 < D_DIM / 4; d4++) {
            float4 wa = w0[d4], wb = w1[d4];
#pragma unroll
            for (int q = 0; q < 8; q++) {
                float4 x = ((const float4*)inp[q])[d4];
                a0[q] += wa.x * x.x + wa.y * x.y + wa.z * x.z + wa.w * x.w;
                a1[q] += wb.x * x.x + wb.y * x.y + wb.z * x.z + wb.w * x.w;
            }
        }
        float ba = gb[h0], bb = gb[h1];
#pragma unroll
        for (int q = 0; q < 8; q++) {
            gata[q] = 1.0f / (1.0f + expf(-(a0[q] + ba)));
            gatb[q] = 1.0f / (1.0f + expf(-(a1[q] + bb)));
        }
    }
    {
        float ba = bhh[h0], bb = bhh[h1];
#pragma unroll
        for (int q = 0; q < 8; q++) {
            hbuf[0][q][h0] = tanhf(xp0a[q] + ba);
            hbuf[0][q][h1] = tanhf(xp0b[q] + bb);
        }
    }
    __syncthreads();

    int cur = 0;
    for (int t = 1; t <= TOPK; t++) {
        for (int i = tid; i < 8 * D_DIM; i += 256) {
            int q = i / D_DIM, d = i % D_DIM;
            int mi = g_topk[(qb + q) * TOPK + (t - 1)];
            inp[q][d] = mem[(size_t)mi * D_DIM + d];
        }
        __syncthreads();

        float a0[8], a1[8];
#pragma unroll
        for (int q = 0; q < 8; q++) { a0[q] = 0.f; a1[q] = 0.f; }
        {
            const float4* w0 = (const float4*)(Wih + (size_t)h0 * D_DIM);
            const float4* w1 = (const float4*)(Wih + (size_t)h1 * D_DIM);
            for (int d4 = 0; d4 < D_DIM / 4; d4++) {
                float4 wa = w0[d4], wb = w1[d4];
#pragma unroll
                for (int q = 0; q < 8; q++) {
                    float4 x = ((const float4*)inp[q])[d4];
                    a0[q] += wa.x * x.x + wa.y * x.y + wa.z * x.z + wa.w * x.w;
                    a1[q] += wb.x * x.x + wb.y * x.y + wb.z * x.z + wb.w * x.w;
                }
            }
        }
        {
            const float4* w0 = (const float4*)(Whh + (size_t)h0 * H_DIM);
            const float4* w1 = (const float4*)(Whh + (size_t)h1 * H_DIM);
            for (int d4 = 0; d4 < H_DIM / 4; d4++) {
                float4 wa = w0[d4], wb = w1[d4];
#pragma unroll
                for (int q = 0; q < 8; q++) {
                    float4 hh = ((const float4*)hbuf[cur][q])[d4];
                    a0[q] += wa.x * hh.x + wa.y * hh.y + wa.z * hh.z + wa.w * hh.w;
                    a1[q] += wb.x * hh.x + wb.y * hh.y + wb.z * hh.z + wb.w * hh.w;
                }
            }
        }
        float bia = bih[h0], bib = bih[h1];
        float bha = bhh[h0], bhb = bhh[h1];
#pragma unroll
        for (int q = 0; q < 8; q++) {
            hbuf[cur ^ 1][q][h0] = tanhf(a0[q] + bia + bha);
            hbuf[cur ^ 1][q][h1] = tanhf(a1[q] + bib + bhb);
        }
        __syncthreads();
        cur ^= 1;
    }

#pragma unroll
    for (int q = 0; q < 8; q++) {
        float ha = hbuf[cur][q][h0];
        float hb = hbuf[cur][q][h1];
        out[(size_t)(qb + q) * H_DIM + h0] = gata[q] * ha + (1.0f - gata[q]) * xp0a[q];
        out[(size_t)(qb + q) * H_DIM + h1] = gatb[q] * hb + (1.0f - gatb[q]) * xp0b[q];
    }
}

// ---------------- launch ----------------
extern "C" void kernel_launch(void* const* d_in, const int* in_sizes, int n_in,
                              void* d_out, int out_size) {
    const float* query  = (const float*)d_in[0];
    const float* mem    = (const float*)d_in[1];
    const float* coords = (const float*)d_in[2];
    const float* sw     = (const float*)d_in[3];
    const float* Wih    = (const float*)d_in[4];
    const float* bih    = (const float*)d_in[5];
    const float* Whh    = (const float*)d_in[6];
    const float* bhh    = (const float*)d_in[7];
    const float* gW     = (const float*)d_in[8];
    const float* gb     = (const float*)d_in[9];
    float* out = (float*)d_out;

    cudaFuncSetAttribute(k_sims_mma, cudaFuncAttributeMaxDynamicSharedMemorySize, SMEM_SIMS);

    k_center<<<1, 256>>>(sw);
    k_act<<<(M_MEM + 255) / 256, 256>>>(coords);
    k_qnorm<<<B_Q, 128>>>(query);
    k_sims_mma<<<NSLAB, 512, SMEM_SIMS>>>(mem);
    k_merge<<<B_Q, 256>>>();
    k_rnn<<<32, 256>>>(query, mem, Wih, bih, Whh, bhh, gW, gb, out);
}

// round 5
// speedup vs baseline: 2.2488x; 1.7371x over previous
#include <cuda_runtime.h>
#include <cuda_bf16.h>
#include <math.h>
#include <stdint.h>

// Problem constants
#define B_Q   256
#define M_MEM 200000
#define D_DIM 384
#define H_DIM 512
#define TOPK  5
#define TM    128
#define NSLAB ((M_MEM + TM - 1) / TM)   // 1563

// ---------------- device scratch ----------------
__device__ float g_center[2];
__device__ float g_act[M_MEM];
__device__ __align__(16) __nv_bfloat16 g_qhi[B_Q * D_DIM];
__device__ __align__(16) __nv_bfloat16 g_qlo[B_Q * D_DIM];
__device__ float g_cand_val[(size_t)NSLAB * B_Q * TOPK];
__device__ int   g_cand_idx[(size_t)NSLAB * B_Q * TOPK];
__device__ int   g_topk[B_Q * TOPK];
// RNN path scratch
__device__ __align__(16) __nv_bfloat16 g_whh_h[H_DIM * H_DIM];
__device__ __align__(16) __nv_bfloat16 g_whh_l[H_DIM * H_DIM];
__device__ __align__(16) __nv_bfloat16 g_wcat_h[1024 * D_DIM];
__device__ __align__(16) __nv_bfloat16 g_wcat_l[1024 * D_DIM];
__device__ float g_xp[1536 * 1024];
__device__ __align__(16) __nv_bfloat16 g_hbh[2][B_Q * H_DIM];
__device__ __align__(16) __nv_bfloat16 g_hbl[2][B_Q * H_DIM];
__device__ float g_hf[B_Q * H_DIM];

// ---------------- helpers ----------------
__device__ __forceinline__ uint32_t smem_u32(const void* p) {
    uint32_t a;
    asm("{ .reg .u64 t; cvta.to.shared.u64 t, %1; cvt.u32.u64 %0, t; }" : "=r"(a) : "l"(p));
    return a;
}
#define CPA16(s, g)  asm volatile("cp.async.cg.shared.global [%0], [%1], 16;" :: "r"(s), "l"(g) : "memory")
#define CPA_COMMIT() asm volatile("cp.async.commit_group;" ::: "memory")
#define CPA_WAIT0()  asm volatile("cp.async.wait_group 0;" ::: "memory")

__device__ __forceinline__ void ldsm4(uint32_t* r, uint32_t addr) {
    asm volatile("ldmatrix.sync.aligned.m8n8.x4.shared.b16 {%0,%1,%2,%3}, [%4];"
        : "=r"(r[0]), "=r"(r[1]), "=r"(r[2]), "=r"(r[3]) : "r"(addr));
}
__device__ __forceinline__ void mma16816(float* d, const uint32_t* a, uint32_t b0, uint32_t b1) {
    asm volatile("mma.sync.aligned.m16n8k16.row.col.f32.bf16.bf16.f32 "
        "{%0,%1,%2,%3}, {%4,%5,%6,%7}, {%8,%9}, {%0,%1,%2,%3};"
        : "+f"(d[0]), "+f"(d[1]), "+f"(d[2]), "+f"(d[3])
        : "r"(a[0]), "r"(a[1]), "r"(a[2]), "r"(a[3]), "r"(b0), "r"(b1));
}
// split float -> (hi, lo) bf16 packed words helper
__device__ __forceinline__ void splt2(float x, float y, uint32_t& hw, uint32_t& lw) {
    __nv_bfloat16 hx = __float2bfloat16(x), hy = __float2bfloat16(y);
    __nv_bfloat16 lx = __float2bfloat16(x - __bfloat162float(hx));
    __nv_bfloat16 ly = __float2bfloat16(y - __bfloat162float(hy));
    __nv_bfloat162 hp = __halves2bfloat162(hx, hy);
    __nv_bfloat162 lp = __halves2bfloat162(lx, ly);
    hw = *(uint32_t*)&hp; lw = *(uint32_t*)&lp;
}

__device__ __forceinline__ bool better(float v, int i, float w, int j) {
    return (v > w) || (v == w && i < j);
}
__device__ __forceinline__ void ins5(float v, int i, float tv[TOPK], int ti[TOPK]) {
    if (!better(v, i, tv[TOPK - 1], ti[TOPK - 1])) return;
#pragma unroll
    for (int r = 0; r < TOPK; r++) {
        if (better(v, i, tv[r], ti[r])) {
            float fv = tv[r]; int fi = ti[r];
            tv[r] = v; ti[r] = i;
            v = fv; i = fi;
        }
    }
}

// ---------------- kernel A0: center ----------------
__global__ void k_center(const float* __restrict__ sw) {
    __shared__ float sx[256], sy[256];
    int tid = threadIdx.x;
    float x = 0.f, y = 0.f;
    for (int i = tid; i < H_DIM; i += 256) { x += sw[2 * i]; y += sw[2 * i + 1]; }
    sx[tid] = x; sy[tid] = y;
    __syncthreads();
    for (int o = 128; o > 0; o >>= 1) {
        if (tid < o) { sx[tid] += sx[tid + o]; sy[tid] += sy[tid + o]; }
        __syncthreads();
    }
    if (tid == 0) {
        g_center[0] = sx[0] / (float)H_DIM;
        g_center[1] = sy[0] / (float)H_DIM;
    }
}

// ---------------- kernel A1: activations ----------------
__global__ void k_act(const float* __restrict__ coords) {
    int i = blockIdx.x * blockDim.x + threadIdx.x;
    if (i < M_MEM) {
        float dx = coords[2 * i]     - g_center[0];
        float dy = coords[2 * i + 1] - g_center[1];
        g_act[i] = 1.0f / (1.0f + sqrtf(dx * dx + dy * dy));
    }
}

// ---------------- kernel A2: normalize queries -> bf16 hi/lo ----------------
__global__ void k_qnorm(const float* __restrict__ q) {
    __shared__ float red[128];
    int b = blockIdx.x, tid = threadIdx.x;
    float s = 0.f;
    for (int d = tid; d < D_DIM; d += 128) {
        float v = q[(size_t)b * D_DIM + d];
        s += v * v;
    }
    red[tid] = s;
    __syncthreads();
    for (int o = 64; o > 0; o >>= 1) {
        if (tid < o) red[tid] += red[tid + o];
        __syncthreads();
    }
    float r = 1.0f / fmaxf(sqrtf(red[0]), 1e-8f);
    for (int d = tid; d < D_DIM; d += 128) {
        float qn = q[(size_t)b * D_DIM + d] * r;
        __nv_bfloat16 h = __float2bfloat16(qn);
        g_qhi[(size_t)b * D_DIM + d] = h;
        g_qlo[(size_t)b * D_DIM + d] = __float2bfloat16(qn - __bfloat162float(h));
    }
}

// ---------------- kernel A3: weight split prep ----------------
__global__ void k_prep(const float* __restrict__ Whh, const float* __restrict__ Wih,
                       const float* __restrict__ gW) {
    int i = blockIdx.x * blockDim.x + threadIdx.x;
    if (i < H_DIM * H_DIM) {
        float v = Whh[i];
        __nv_bfloat16 h = __float2bfloat16(v);
        g_whh_h[i] = h;
        g_whh_l[i] = __float2bfloat16(v - __bfloat162float(h));
    } else if (i < H_DIM * H_DIM + 1024 * D_DIM) {
        int j = i - H_DIM * H_DIM;
        int row = j / D_DIM, col = j % D_DIM;
        float v = (row < 512) ? Wih[row * D_DIM + col] : gW[(row - 512) * D_DIM + col];
        __nv_bfloat16 h = __float2bfloat16(v);
        g_wcat_h[j] = h;
        g_wcat_l[j] = __float2bfloat16(v - __bfloat162float(h));
    }
}

// ---------------- kernel B: pipelined mma sims + fused norms + top-5 ----------------
// chunk K=64 bf16, PADB=144 per row. Stage: Ahi|Alo|Bhi|Blo.
#define S_AHI 0
#define S_ALO 18432
#define S_BHI 36864
#define S_BLO 73728
#define STG_SZ 110592
#define HDR   4096
#define SIMS_SMEM (HDR + 2 * STG_SZ)   // 225280
// epilogue reuse:
#define E_STG HDR
#define E_PV  (HDR + 135168)
#define E_PI  (E_PV + 10240)

__global__ __launch_bounds__(512, 1) void k_sims_mma(const float* __restrict__ mem) {
    extern __shared__ char smem[];
    const uint32_t sb = smem_u32(smem);
    float* s_rn  = (float*)smem;
    float* s_act = (float*)(smem + 512);
    float* s_red = (float*)(smem + 1024);

    const int tid = threadIdx.x;
    const int l   = tid & 31;
    const int w   = tid >> 5;
    const int wm  = w & 3;
    const int wn  = w >> 2;        // 0..3, 64 cols each
    const int m0  = blockIdx.x * TM;

    if (tid < 128) {
        bool ok = (m0 + tid) < M_MEM;
        s_act[tid] = ok ? g_act[m0 + tid] : -1e30f;
    }

    float acc[2][8][4];
#pragma unroll
    for (int a = 0; a < 2; a++)
#pragma unroll
        for (int p = 0; p < 8; p++)
#pragma unroll
            for (int r = 0; r < 4; r++) acc[a][p][r] = 0.f;

    const int arow = tid >> 2, aq = tid & 3;
    int arg = m0 + arow; if (arg >= M_MEM) arg = M_MEM - 1;
    const float4* asrc = (const float4*)(mem + (size_t)arg * D_DIM + aq * 16);

    float nsq = 0.f;
    float4 pf[4];

    const uint32_t aoff = (uint32_t)((wm * 32 + (l & 15)) * 144 + (l >> 4) * 16);
    const uint32_t boff = (uint32_t)((wn * 64 + (l & 15)) * 144 + (l >> 4) * 16);
    const uint32_t asts = (uint32_t)(arow * 144 + aq * 32);

    // ---- prologue: chunk 0 ----
    {
        const uint32_t st = sb + HDR;
#pragma unroll
        for (int i = 0; i < 4; i++) {
            int idx = i * 512 + tid;
            int row = idx >> 3, s = idx & 7;
            uint32_t d = st + (uint32_t)(row * 144 + s * 16);
            size_t go = (size_t)row * D_DIM + s * 8;
            CPA16(d + S_BHI, (const void*)(g_qhi + go));
            CPA16(d + S_BLO, (const void*)(g_qlo + go));
        }
        CPA_COMMIT();
#pragma unroll
        for (int i = 0; i < 4; i++) pf[i] = asrc[i];
    }
    // convert+STS chunk0 A, accumulate norms
    {
        char* stc = smem + HDR;
#pragma unroll
        for (int i = 0; i < 2; i++) {
            uint32_t hw[4], lw[4];
#pragma unroll
            for (int j = 0; j < 2; j++) {
                float4 v = pf[2 * i + j];
                nsq += v.x * v.x + v.y * v.y + v.z * v.z + v.w * v.w;
                splt2(v.x, v.y, hw[2 * j], lw[2 * j]);
                splt2(v.z, v.w, hw[2 * j + 1], lw[2 * j + 1]);
            }
            *(uint4*)(stc + S_AHI + asts + i * 16) = make_uint4(hw[0], hw[1], hw[2], hw[3]);
            *(uint4*)(stc + S_ALO + asts + i * 16) = make_uint4(lw[0], lw[1], lw[2], lw[3]);
        }
    }
    CPA_WAIT0();
    __syncthreads();

    // ---- main loop: 6 chunks of K=64 ----
#pragma unroll 1
    for (int c = 0; c < 6; c++) {
        const int buf = c & 1;
        const uint32_t st  = sb + HDR + buf * STG_SZ;
        if (c < 5) {
            const uint32_t stn = sb + HDR + (buf ^ 1) * STG_SZ;
#pragma unroll
            for (int i = 0; i < 4; i++) {
                int idx = i * 512 + tid;
                int row = idx >> 3, s = idx & 7;
                uint32_t d = stn + (uint32_t)(row * 144 + s * 16);
                size_t go = (size_t)row * D_DIM + (c + 1) * 64 + s * 8;
                CPA16(d + S_BHI, (const void*)(g_qhi + go));
                CPA16(d + S_BLO, (const void*)(g_qlo + go));
            }
            CPA_COMMIT();
#pragma unroll
            for (int i = 0; i < 4; i++) pf[i] = asrc[(c + 1) * 16 + i];
        }

        // GEMM: 4 k16 steps
        const uint32_t aB = st + S_AHI + aoff;
        const uint32_t bB = st + S_BHI + boff;
#pragma unroll
        for (int kk = 0; kk < 4; kk++) {
            uint32_t bh[16], bl[16];
#pragma unroll
            for (int pp = 0; pp < 4; pp++) {
                uint32_t ba = bB + (uint32_t)(pp * 16 * 144 + kk * 32);
                ldsm4(bh + pp * 4, ba);
                ldsm4(bl + pp * 4, ba + (S_BLO - S_BHI));
            }
#pragma unroll
            for (int a = 0; a < 2; a++) {
                uint32_t ah4[4], al4[4];
                uint32_t aa = aB + (uint32_t)(a * 16 * 144 + kk * 32);
                ldsm4(ah4, aa);
                ldsm4(al4, aa + (S_ALO - S_AHI));
#pragma unroll
                for (int p = 0; p < 8; p++) {
                    int pp = p >> 1, hi = p & 1;
                    uint32_t b0h = bh[pp * 4 + hi], b1h = bh[pp * 4 + hi + 2];
                    uint32_t b0l = bl[pp * 4 + hi], b1l = bl[pp * 4 + hi + 2];
                    mma16816(acc[a][p], ah4, b0h, b1h);
                    mma16816(acc[a][p], ah4, b0l, b1l);
                    mma16816(acc[a][p], al4, b0h, b1h);
                }
            }
        }

        if (c < 5) {
            CPA_WAIT0();
            __syncthreads();
            char* stcn = smem + HDR + (buf ^ 1) * STG_SZ;
#pragma unroll
            for (int i = 0; i < 2; i++) {
                uint32_t hw[4], lw[4];
#pragma unroll
                for (int j = 0; j < 2; j++) {
                    float4 v = pf[2 * i + j];
                    nsq += v.x * v.x + v.y * v.y + v.z * v.z + v.w * v.w;
                    splt2(v.x, v.y, hw[2 * j], lw[2 * j]);
                    splt2(v.z, v.w, hw[2 * j + 1], lw[2 * j + 1]);
                }
                *(uint4*)(stcn + S_AHI + asts + i * 16) = make_uint4(hw[0], hw[1], hw[2], hw[3]);
                *(uint4*)(stcn + S_ALO + asts + i * 16) = make_uint4(lw[0], lw[1], lw[2], lw[3]);
            }
            __syncthreads();
        }
    }

    // ---- norms reduce ----
    __syncthreads();
    s_red[tid] = nsq;
    __syncthreads();
    if (tid < 128) {
        float s = s_red[4 * tid] + s_red[4 * tid + 1] + s_red[4 * tid + 2] + s_red[4 * tid + 3];
        bool ok = (m0 + tid) < M_MEM;
        s_rn[tid] = ok ? 1.0f / fmaxf(sqrtf(s), 1e-8f) : 0.0f;
    }
    __syncthreads();

    // ---- epilogue: scale + bias, stage query-major, fused top-5 ----
    float* stg = (float*)(smem + E_STG);
#pragma unroll
    for (int a = 0; a < 2; a++) {
        int mA = wm * 32 + a * 16 + (l >> 2);
        float rnA = s_rn[mA],     acA = s_act[mA];
        float rnB = s_rn[mA + 8], acB = s_act[mA + 8];
#pragma unroll
        for (int p = 0; p < 8; p++) {
            int q = wn * 64 + p * 8 + (l & 3) * 2;
            stg[q * 132 + mA]           = acc[a][p][0] * rnA + acA;
            stg[(q + 1) * 132 + mA]     = acc[a][p][1] * rnA + acA;
            stg[q * 132 + mA + 8]       = acc[a][p][2] * rnB + acB;
            stg[(q + 1) * 132 + mA + 8] = acc[a][p][3] * rnB + acB;
        }
    }
    __syncthreads();

    {
        float* pv = (float*)(smem + E_PV);
        int*   pi = (int*)(smem + E_PI);
        int q = tid >> 1, h = tid & 1;
        float tv[TOPK]; int ti[TOPK];
#pragma unroll
        for (int r = 0; r < TOPK; r++) { tv[r] = -3.4e38f; ti[r] = 0x7fffffff; }
        const float4* col = (const float4*)(stg + q * 132 + h * 64);
#pragma unroll 4
        for (int i = 0; i < 16; i++) {
            float4 v = col[i];
            int mb = m0 + h * 64 + i * 4;
            ins5(v.x, mb,     tv, ti);
            ins5(v.y, mb + 1, tv, ti);
            ins5(v.z, mb + 2, tv, ti);
            ins5(v.w, mb + 3, tv, ti);
        }
#pragma unroll
        for (int r = 0; r < TOPK; r++) { pv[tid * TOPK + r] = tv[r]; pi[tid * TOPK + r] = ti[r]; }
        __syncthreads();

        if (tid < 256) {
            float fv[TOPK]; int fi[TOPK];
#pragma unroll
            for (int r = 0; r < TOPK; r++) {
                fv[r] = pv[(2 * tid) * TOPK + r];
                fi[r] = pi[(2 * tid) * TOPK + r];
            }
#pragma unroll
            for (int r = 0; r < TOPK; r++)
                ins5(pv[(2 * tid + 1) * TOPK + r], pi[(2 * tid + 1) * TOPK + r], fv, fi);
            size_t base = ((size_t)blockIdx.x * B_Q + tid) * TOPK;
#pragma unroll
            for (int r = 0; r < TOPK; r++) {
                g_cand_val[base + r] = fv[r];
                g_cand_idx[base + r] = fi[r];
            }
        }
    }
}

// ---------------- kernel C: merge ----------------
__device__ __forceinline__ void merge5(float* av, int* ai, const float* bv, const int* bi) {
    float ov[TOPK]; int oi[TOPK];
    int ia = 0, ib = 0;
#pragma unroll
    for (int r = 0; r < TOPK; r++) {
        bool ta = (ib >= TOPK) || (ia < TOPK && better(av[ia], ai[ia], bv[ib], bi[ib]));
        if (ta) { ov[r] = av[ia]; oi[r] = ai[ia]; ia++; }
        else    { ov[r] = bv[ib]; oi[r] = bi[ib]; ib++; }
    }
#pragma unroll
    for (int r = 0; r < TOPK; r++) { av[r] = ov[r]; ai[r] = oi[r]; }
}

__global__ void k_merge() {
    const int q = blockIdx.x, tid = threadIdx.x;
    float tv[TOPK]; int ti[TOPK];
#pragma unroll
    for (int r = 0; r < TOPK; r++) { tv[r] = -3.4e38f; ti[r] = 0x7fffffff; }
    for (int s = tid; s < NSLAB; s += 256) {
        size_t base = ((size_t)s * B_Q + q) * TOPK;
#pragma unroll
        for (int r = 0; r < TOPK; r++)
            ins5(g_cand_val[base + r], g_cand_idx[base + r], tv, ti);
    }
    __shared__ float sv[256][TOPK];
    __shared__ int   si[256][TOPK];
#pragma unroll
    for (int r = 0; r < TOPK; r++) { sv[tid][r] = tv[r]; si[tid][r] = ti[r]; }
    __syncthreads();
    for (int o = 128; o > 0; o >>= 1) {
        if (tid < o) merge5(sv[tid], si[tid], sv[tid + o], si[tid + o]);
        __syncthreads();
    }
    if (tid == 0) {
#pragma unroll
        for (int r = 0; r < TOPK; r++)
            g_topk[q * TOPK + r] = si[0][r];
    }
}

// ---------------- kernel D1: x_proj + gate GEMM [1536 x 1024 x 384] ----------------
#define XP_AHI 0
#define XP_ALO 34816
#define XP_BHI 69632
#define XP_BLO 104448
#define XP_SMEM 139264

__global__ __launch_bounds__(256, 1) void k_xproj(
    const float* __restrict__ query, const float* __restrict__ mem,
    const float* __restrict__ bih, const float* __restrict__ gb)
{
    extern __shared__ char smem[];
    const uint32_t sb = smem_u32(smem);
    const int tid = threadIdx.x, l = tid & 31, w = tid >> 5;
    const int wm = w & 3, wn = w >> 2;   // wn 0..1
    const int bm = blockIdx.x, bn = blockIdx.y;

    // A gather pointer (one row per 2 threads)
    const int lrow = tid >> 1, kh = tid & 1;
    int r = bm * 128 + lrow;
    int t = r >> 8, q = r & 255;
    const float* aptr;
    if (t == 0) aptr = query + (size_t)q * D_DIM;
    else        aptr = mem + (size_t)g_topk[q * TOPK + t - 1] * D_DIM;
    aptr += kh * 64;

    float acc[2][8][4];
#pragma unroll
    for (int a = 0; a < 2; a++)
#pragma unroll
        for (int p = 0; p < 8; p++)
#pragma unroll
            for (int rr = 0; rr < 4; rr++) acc[a][p][rr] = 0.f;

#pragma unroll 1
    for (int c = 0; c < 3; c++) {
        __syncthreads();
        // B tile: 128 rows x 128 bf16 chunk = 256 bytes/row -> 16 segs of 16B
#pragma unroll
        for (int i = 0; i < 8; i++) {
            int idx = i * 256 + tid;
            int row = idx >> 4, s = idx & 15;
            uint32_t d = sb + (uint32_t)(row * 272 + s * 16);
            size_t go = (size_t)(bn * 128 + row) * D_DIM + c * 128 + s * 8;
            CPA16(d + XP_BHI, (const void*)(g_wcat_h + go));
            CPA16(d + XP_BLO, (const void*)(g_wcat_l + go));
        }
        CPA_COMMIT();
        {
            char* ah = smem + XP_AHI;
            char* al = smem + XP_ALO;
            const float4* src = (const float4*)(aptr + c * 128);
#pragma unroll
            for (int i = 0; i < 16; i++) {
                float4 v = src[i];
                uint32_t h0, l0, h1, l1;
                splt2(v.x, v.y, h0, l0);
                splt2(v.z, v.w, h1, l1);
                uint32_t so = (uint32_t)(lrow * 272 + kh * 128 + i * 8);
                *(uint2*)(ah + so) = make_uint2(h0, h1);
                *(uint2*)(al + so) = make_uint2(l0, l1);
            }
        }
        CPA_WAIT0();
        __syncthreads();

        const uint32_t aB = sb + XP_AHI + (uint32_t)((wm * 32 + (l & 15)) * 272 + (l >> 4) * 16);
        const uint32_t bB = sb + XP_BHI + (uint32_t)((wn * 64 + (l & 15)) * 272 + (l >> 4) * 16);
#pragma unroll 1
        for (int kk = 0; kk < 8; kk++) {
            uint32_t bh[16], bl[16];
#pragma unroll
            for (int pp = 0; pp < 4; pp++) {
                uint32_t ba = bB + (uint32_t)(pp * 16 * 272 + kk * 32);
                ldsm4(bh + pp * 4, ba);
                ldsm4(bl + pp * 4, ba + (XP_BLO - XP_BHI));
            }
#pragma unroll
            for (int a = 0; a < 2; a++) {
                uint32_t ah4[4], al4[4];
                uint32_t aa = aB + (uint32_t)(a * 16 * 272 + kk * 32);
                ldsm4(ah4, aa);
                ldsm4(al4, aa + (XP_ALO - XP_AHI));
#pragma unroll
                for (int p = 0; p < 8; p++) {
                    int pp = p >> 1, hi = p & 1;
                    mma16816(acc[a][p], ah4, bh[pp * 4 + hi], bh[pp * 4 + hi + 2]);
                    mma16816(acc[a][p], ah4, bl[pp * 4 + hi], bl[pp * 4 + hi + 2]);
                    mma16816(acc[a][p], al4, bh[pp * 4 + hi], bh[pp * 4 + hi + 2]);
                }
            }
        }
    }

    // epilogue: add bias, write g_xp
#pragma unroll
    for (int a = 0; a < 2; a++) {
        int rA = bm * 128 + wm * 32 + a * 16 + (l >> 2);
#pragma unroll
        for (int p = 0; p < 8; p++) {
            int cg = bn * 128 + wn * 64 + p * 8 + (l & 3) * 2;
            float b0 = (cg < 512) ? bih[cg] : gb[cg - 512];
            float b1 = (cg < 512) ? bih[cg + 1] : gb[cg + 1 - 512];
            g_xp[(size_t)rA * 1024 + cg]           = acc[a][p][0] + b0;
            g_xp[(size_t)rA * 1024 + cg + 1]       = acc[a][p][1] + b1;
            g_xp[(size_t)(rA + 8) * 1024 + cg]     = acc[a][p][2] + b0;
            g_xp[(size_t)(rA + 8) * 1024 + cg + 1] = acc[a][p][3] + b1;
        }
    }
}

// ---------------- kernel D2: h0 = tanh(xp[0] + bhh) ----------------
__global__ void k_h0(const float* __restrict__ bhh) {
    int i = blockIdx.x * blockDim.x + threadIdx.x;   // 131072
    int q = i >> 9, h = i & 511;
    float v = tanhf(g_xp[(size_t)q * 1024 + h] + bhh[h]);
    __nv_bfloat16 hi = __float2bfloat16(v);
    g_hbh[0][i] = hi;
    g_hbl[0][i] = __float2bfloat16(v - __bfloat162float(hi));
    g_hf[i] = v;
}

// ---------------- kernel D3: recurrence step GEMM [64 x 128 x 512] per CTA ----------------
#define ST_AHI 0
#define ST_ALO 17408
#define ST_BHI 34816
#define ST_BLO 69632
#define ST_SMEM 104448

__global__ __launch_bounds__(256, 1) void k_step(int t, const float* __restrict__ bhh) {
    extern __shared__ char smem[];
    const uint32_t sb = smem_u32(smem);
    const int tid = threadIdx.x, l = tid & 31, w = tid >> 5;
    const int wm = w & 3, wn = w >> 2;   // warp tile 16 x 64
    const int mt = blockIdx.x, nt = blockIdx.y;
    const int bin = (t + 1) & 1, bout = t & 1;
    const __nv_bfloat16* Ah = g_hbh[bin];
    const __nv_bfloat16* Al = g_hbl[bin];

    float acc[8][4];
#pragma unroll
    for (int p = 0; p < 8; p++)
#pragma unroll
        for (int rr = 0; rr < 4; rr++) acc[p][rr] = 0.f;

#pragma unroll 1
    for (int c = 0; c < 4; c++) {
        __syncthreads();
        // A tile: 64 rows x 256 bytes -> 16 segs/row, 1024 total
#pragma unroll
        for (int i = 0; i < 4; i++) {
            int idx = i * 256 + tid;
            int row = idx >> 4, s = idx & 15;
            uint32_t d = sb + (uint32_t)(row * 272 + s * 16);
            size_t go = (size_t)(mt * 64 + row) * H_DIM + c * 128 + s * 8;
            CPA16(d + ST_AHI, (const void*)(Ah + go));
            CPA16(d + ST_ALO, (const void*)(Al + go));
        }
        // B tile: 128 rows x 256 bytes -> 2048 segs
#pragma unroll
        for (int i = 0; i < 8; i++) {
            int idx = i * 256 + tid;
            int row = idx >> 4, s = idx & 15;
            uint32_t d = sb + ST_BHI + (uint32_t)(row * 272 + s * 16);
            size_t go = (size_t)(nt * 128 + row) * H_DIM + c * 128 + s * 8;
            CPA16(d, (const void*)(g_whh_h + go));
            CPA16(d + (ST_BLO - ST_BHI), (const void*)(g_whh_l + go));
        }
        CPA_COMMIT();
        CPA_WAIT0();
        __syncthreads();

        const uint32_t aB = sb + ST_AHI + (uint32_t)((wm * 16 + (l & 15)) * 272 + (l >> 4) * 16);
        const uint32_t bB = sb + ST_BHI + (uint32_t)((wn * 64 + (l & 15)) * 272 + (l >> 4) * 16);
#pragma unroll 1
        for (int kk = 0; kk < 8; kk++) {
            uint32_t bh[16], bl[16];
#pragma unroll
            for (int pp = 0; pp < 4; pp++) {
                uint32_t ba = bB + (uint32_t)(pp * 16 * 272 + kk * 32);
                ldsm4(bh + pp * 4, ba);
                ldsm4(bl + pp * 4, ba + (ST_BLO - ST_BHI));
            }
            uint32_t ah4[4], al4[4];
            ldsm4(ah4, aB + (uint32_t)(kk * 32));
            ldsm4(al4, aB + (uint32_t)(kk * 32) + (ST_ALO - ST_AHI));
#pragma unroll
            for (int p = 0; p < 8; p++) {
                int pp = p >> 1, hi = p & 1;
                mma16816(acc[p], ah4, bh[pp * 4 + hi], bh[pp * 4 + hi + 2]);
                mma16816(acc[p], ah4, bl[pp * 4 + hi], bl[pp * 4 + hi + 2]);
                mma16816(acc[p], al4, bh[pp * 4 + hi], bh[pp * 4 + hi + 2]);
            }
        }
    }

    // epilogue
    int q0 = mt * 64 + wm * 16 + (l >> 2);
#pragma unroll
    for (int p = 0; p < 8; p++) {
        int h = nt * 128 + wn * 64 + p * 8 + (l & 3) * 2;
#pragma unroll
        for (int rr = 0; rr < 4; rr++) {
            int qq = q0 + ((rr >> 1) ? 8 : 0);
            int hh = h + (rr & 1);
            float v = acc[p][rr] + g_xp[(size_t)(t * 256 + qq) * 1024 + hh] + bhh[hh];
            float ht = tanhf(v);
            size_t o = (size_t)qq * H_DIM + hh;
            g_hf[o] = ht;
            __nv_bfloat16 hb = __float2bfloat16(ht);
            g_hbh[bout][o] = hb;
            g_hbl[bout][o] = __float2bfloat16(ht - __bfloat162float(hb));
        }
    }
}

// ---------------- kernel D4: output gate mix ----------------
__global__ void k_out(float* __restrict__ out) {
    int i = blockIdx.x * blockDim.x + threadIdx.x;   // 131072
    int q = i >> 9, h = i & 511;
    float gpre = g_xp[(size_t)q * 1024 + 512 + h];
    float g = 1.0f / (1.0f + expf(-gpre));
    float proj = g_xp[(size_t)q * 1024 + h];
    out[i] = g * g_hf[i] + (1.0f - g) * proj;
}

// ---------------- launch ----------------
extern "C" void kernel_launch(void* const* d_in, const int* in_sizes, int n_in,
                              void* d_out, int out_size) {
    const float* query  = (const float*)d_in[0];
    const float* mem    = (const float*)d_in[1];
    const float* coords = (const float*)d_in[2];
    const float* sw     = (const float*)d_in[3];
    const float* Wih    = (const float*)d_in[4];
    const float* bih    = (const float*)d_in[5];
    const float* Whh    = (const float*)d_in[6];
    const float* bhh    = (const float*)d_in[7];
    const float* gW     = (const float*)d_in[8];
    const float* gb     = (const float*)d_in[9];
    float* out = (float*)d_out;

    cudaFuncSetAttribute(k_sims_mma, cudaFuncAttributeMaxDynamicSharedMemorySize, SIMS_SMEM);
    cudaFuncSetAttribute(k_xproj,    cudaFuncAttributeMaxDynamicSharedMemorySize, XP_SMEM);
    cudaFuncSetAttribute(k_step,     cudaFuncAttributeMaxDynamicSharedMemorySize, ST_SMEM);

    k_center<<<1, 256>>>(sw);
    k_act<<<(M_MEM + 255) / 256, 256>>>(coords);
    k_qnorm<<<B_Q, 128>>>(query);
    k_prep<<<(H_DIM * H_DIM + 1024 * D_DIM + 255) / 256, 256>>>(Whh, Wih, gW);
    k_sims_mma<<<NSLAB, 512, SIMS_SMEM>>>(mem);
    k_merge<<<B_Q, 256>>>();
    k_xproj<<<dim3(12, 8), 256, XP_SMEM>>>(query, mem, bih, gb);
    k_h0<<<(B_Q * H_DIM) / 256, 256>>>(bhh);
    for (int t = 1; t <= TOPK; t++)
        k_step<<<dim3(4, 4), 256, ST_SMEM>>>(t, bhh);
    k_out<<<(B_Q * H_DIM) / 256, 256>>>(out);
}